// round 1
// baseline (speedup 1.0000x reference)
#include <cuda_runtime.h>
#include <cuda_bf16.h>

// GVCNN group pooling, collapsed to out[n,c] = sum_v coeff[n,v] * RPs[n,v,c].
// One CTA per row n: stage the 12x256 f32 tile (12 KB) in shared, compute the
// 12 view scores (dot with w), derive the 12 coefficients via the bin logic,
// then emit the weighted sum. RPs is read exactly once -> HBM-bound.

#define NV 12
#define NC 256
#define NG 5
#define EPSF 1e-6f

__global__ __launch_bounds__(256, 8)
void gvcnn_kernel(const float* __restrict__ RPs,
                  const float* __restrict__ w,
                  const float* __restrict__ b,
                  float* __restrict__ out)
{
    __shared__ float s_tile[NV * NC];   // 12 KB row tile
    __shared__ float s_w[NC];
    __shared__ float s_warp[8][NV];     // per-warp dot partials
    __shared__ float s_coeff[NV];

    const int n   = blockIdx.x;
    const int tid = threadIdx.x;

    // ---- Phase 1: load tile (float4, coalesced) + weights ----
    const float4* src = reinterpret_cast<const float4*>(RPs + (size_t)n * (NV * NC));
    float4*       dst = reinterpret_cast<float4*>(s_tile);
    #pragma unroll
    for (int i = 0; i < (NV * NC / 4) / 256; ++i)   // 3 iters
        dst[tid + i * 256] = src[tid + i * 256];
    s_w[tid] = w[tid];
    __syncthreads();

    // ---- Phase 2: per-view dot products. Thread t owns channel t. ----
    const float wt = s_w[tid];
    float part[NV];
    #pragma unroll
    for (int v = 0; v < NV; ++v)
        part[v] = s_tile[v * NC + tid] * wt;

    #pragma unroll
    for (int off = 16; off > 0; off >>= 1) {
        #pragma unroll
        for (int v = 0; v < NV; ++v)
            part[v] += __shfl_down_sync(0xffffffffu, part[v], off);
    }
    const int warp = tid >> 5, lane = tid & 31;
    if (lane == 0) {
        #pragma unroll
        for (int v = 0; v < NV; ++v)
            s_warp[warp][v] = part[v];
    }
    __syncthreads();

    // ---- Phase 3: bin logic (scalar, tiny) ----
    if (tid == 0) {
        float score[NV];
        int   gid[NV];
        float gsize[NG] = {0.f, 0.f, 0.f, 0.f, 0.f};
        const float bb = b[0];
        #pragma unroll
        for (int v = 0; v < NV; ++v) {
            float y = bb;
            #pragma unroll
            for (int wr = 0; wr < 8; ++wr) y += s_warp[wr][v];
            float x = fabsf(y) + EPSF;
            float t = logf(x);
            float s = 1.0f / (1.0f + expf(-t));      // sigmoid(log(x)), matches ref
            score[v] = s;
            int g = min((int)(s * 10.0f), 9) >> 1;   // floor, clamp 9, //2
            gid[v] = g;
            gsize[g] += 1.0f;
        }
        float gscore[NG];
        float ssum = 0.f;
        #pragma unroll
        for (int g = 0; g < NG; ++g) {
            float acc = 0.f;
            #pragma unroll
            for (int v = 0; v < NV; ++v)
                if (gid[v] == g) acc += ceilf(score[v] * gsize[g]);
            gscore[g] = acc / (gsize[g] + EPSF);
            ssum += gscore[g];
        }
        const float inv = 1.0f / (ssum + EPSF);
        #pragma unroll
        for (int v = 0; v < NV; ++v)
            s_coeff[v] = gscore[gid[v]] * inv / (gsize[gid[v]] + EPSF);
    }
    __syncthreads();

    // ---- Phase 4: weighted sum over views, thread t = channel t ----
    float c0 = s_coeff[0];
    float acc = c0 * s_tile[tid];
    #pragma unroll
    for (int v = 1; v < NV; ++v)
        acc += s_coeff[v] * s_tile[v * NC + tid];
    out[(size_t)n * NC + tid] = acc;
}

extern "C" void kernel_launch(void* const* d_in, const int* in_sizes, int n_in,
                              void* d_out, int out_size)
{
    const float* RPs = (const float*)d_in[0];
    const float* w   = (const float*)d_in[1];
    const float* b   = (const float*)d_in[2];
    float*       out = (float*)d_out;
    (void)in_sizes; (void)n_in; (void)out_size;

    gvcnn_kernel<<<8192, 256>>>(RPs, w, b, out);
}

// round 2
// speedup vs baseline: 1.2970x; 1.2970x over previous
#include <cuda_runtime.h>
#include <cuda_bf16.h>

// GVCNN group pooling collapsed to out[n,c] = sum_v coeff[n,v] * RPs[n,v,c].
// One CTA (256 threads) per row n. Thread t owns channel t:
//   - 12 coalesced scalar loads keep the whole row slice in REGISTERS
//   - per-view dot via warp shuffles + tiny smem cross-warp combine
//   - transcendental score math parallelized across 12 lanes of warp 0
//   - weighted sum straight from registers, one coalesced store
// RPs is touched exactly once in global AND shared is only used for 2 tiny
// reduction buffers -> should be DRAM-latency/throughput bound.

#define NV 12
#define NC 256
#define NG 5
#define EPSF 1e-6f

__global__ __launch_bounds__(256, 6)
void gvcnn_kernel(const float* __restrict__ RPs,
                  const float* __restrict__ w,
                  const float* __restrict__ b,
                  float* __restrict__ out)
{
    __shared__ float s_red[8][NV];     // per-warp dot partials
    __shared__ float s_score[NV];
    __shared__ int   s_gid[NV];
    __shared__ float s_coeff[NV];

    const int n    = blockIdx.x;
    const int tid  = threadIdx.x;
    const int warp = tid >> 5;
    const int lane = tid & 31;

    const float* row = RPs + (size_t)n * (NV * NC);

    // ---- Load row slice into registers (12 independent coalesced LDGs) ----
    float r[NV];
    #pragma unroll
    for (int v = 0; v < NV; ++v)
        r[v] = row[v * NC + tid];
    const float wt = __ldg(w + tid);

    // ---- Per-view dot partials + warp-level tree reduce ----
    float part[NV];
    #pragma unroll
    for (int v = 0; v < NV; ++v)
        part[v] = r[v] * wt;

    #pragma unroll
    for (int off = 16; off > 0; off >>= 1) {
        #pragma unroll
        for (int v = 0; v < NV; ++v)
            part[v] += __shfl_down_sync(0xffffffffu, part[v], off);
    }
    if (lane == 0) {
        #pragma unroll
        for (int v = 0; v < NV; ++v)
            s_red[warp][v] = part[v];
    }
    __syncthreads();

    // ---- Scores: lane v of warp 0 handles view v (parallel transcendentals) ----
    if (warp == 0) {
        if (lane < NV) {
            float y = b[0];
            #pragma unroll
            for (int wr = 0; wr < 8; ++wr)
                y += s_red[wr][lane];
            float x = fabsf(y) + EPSF;
            float t = logf(x);
            float s = 1.0f / (1.0f + expf(-t));      // sigmoid(log(x)), matches ref
            s_score[lane] = s;
            s_gid[lane]   = min((int)(s * 10.0f), 9) >> 1;
        }
        __syncwarp();
        if (lane == 0) {
            // cheap serial group aggregation (~60 simple ops)
            float gsize[NG] = {0.f, 0.f, 0.f, 0.f, 0.f};
            #pragma unroll
            for (int v = 0; v < NV; ++v)
                gsize[s_gid[v]] += 1.0f;
            float gscore[NG];
            float ssum = 0.f;
            #pragma unroll
            for (int g = 0; g < NG; ++g) {
                float acc = 0.f;
                #pragma unroll
                for (int v = 0; v < NV; ++v)
                    if (s_gid[v] == g) acc += ceilf(s_score[v] * gsize[g]);
                gscore[g] = acc / (gsize[g] + EPSF);
                ssum += gscore[g];
            }
            const float inv = 1.0f / (ssum + EPSF);
            #pragma unroll
            for (int v = 0; v < NV; ++v)
                s_coeff[v] = gscore[s_gid[v]] * inv / (gsize[s_gid[v]] + EPSF);
        }
    }
    __syncthreads();

    // ---- Weighted sum straight from registers, coalesced store ----
    float acc = 0.f;
    #pragma unroll
    for (int v = 0; v < NV; ++v)
        acc += s_coeff[v] * r[v];
    out[(size_t)n * NC + tid] = acc;
}

extern "C" void kernel_launch(void* const* d_in, const int* in_sizes, int n_in,
                              void* d_out, int out_size)
{
    const float* RPs = (const float*)d_in[0];
    const float* w   = (const float*)d_in[1];
    const float* b   = (const float*)d_in[2];
    float*       out = (float*)d_out;
    (void)in_sizes; (void)n_in; (void)out_size;

    gvcnn_kernel<<<8192, 256>>>(RPs, w, b, out);
}

// round 3
// speedup vs baseline: 1.3426x; 1.0351x over previous
#include <cuda_runtime.h>
#include <cuda_bf16.h>

// GVCNN group pooling: out[n,c] = sum_v coeff[n,v] * RPs[n,v,c].
// 64 threads per row, 4 channels per thread (float4). Per CTA: 4 rows.
//   - 12 LDG.128 per thread (row slice lives in registers)
//   - per-view dot: 4-channel register pre-reduce + 5-round shuffle tree
//     (4x less MIO/SHFL work per row than thread-per-channel layout)
//   - transcendental score math on 12 parallel lanes, tiny serial bin tail
//   - weighted sum from registers, one STG.128 per thread
// MIO (shfl+LDG instruction count) was the binding pipe; this cuts it 4x.

#define NV 12
#define NC 256
#define NG 5
#define ROWS_PER_CTA 4
#define EPSF 1e-6f

__global__ __launch_bounds__(256, 4)
void gvcnn_kernel(const float* __restrict__ RPs,
                  const float* __restrict__ w,
                  const float* __restrict__ b,
                  float* __restrict__ out)
{
    __shared__ float s_red[ROWS_PER_CTA][2][NV];   // per-warp dot partials
    __shared__ float s_score[ROWS_PER_CTA][NV];
    __shared__ int   s_gid[ROWS_PER_CTA][NV];
    __shared__ float s_coeff[ROWS_PER_CTA][NV];

    const int tid  = threadIdx.x;
    const int grp  = tid >> 6;          // row group 0..3
    const int gt   = tid & 63;          // thread within group
    const int gw   = gt >> 5;           // warp within group (0/1)
    const int lane = tid & 31;
    const int n    = blockIdx.x * ROWS_PER_CTA + grp;

    // ---- Load row slice into registers: 12 x LDG.128, coalesced ----
    const float4* row4 = reinterpret_cast<const float4*>(RPs + (size_t)n * (NV * NC));
    float4 r[NV];
    #pragma unroll
    for (int v = 0; v < NV; ++v)
        r[v] = row4[v * (NC / 4) + gt];
    const float4 w4 = reinterpret_cast<const float4*>(w)[gt];

    // ---- Per-view 4-channel dot pre-reduce (FMA pipe) ----
    float part[NV];
    #pragma unroll
    for (int v = 0; v < NV; ++v) {
        float p = r[v].x * w4.x;
        p = fmaf(r[v].y, w4.y, p);
        p = fmaf(r[v].z, w4.z, p);
        part[v] = fmaf(r[v].w, w4.w, p);
    }

    // ---- Warp shuffle tree (5 rounds x 12 views) ----
    #pragma unroll
    for (int off = 16; off > 0; off >>= 1) {
        #pragma unroll
        for (int v = 0; v < NV; ++v)
            part[v] += __shfl_down_sync(0xffffffffu, part[v], off);
    }
    if (lane == 0) {
        #pragma unroll
        for (int v = 0; v < NV; ++v)
            s_red[grp][gw][v] = part[v];
    }
    __syncthreads();

    // ---- Scores: lanes 0..11 of warp 0 of each group, then serial bin tail ----
    if (gw == 0) {
        if (lane < NV) {
            float y = s_red[grp][0][lane] + s_red[grp][1][lane] + b[0];
            float x = fabsf(y) + EPSF;
            float t = logf(x);
            float s = 1.0f / (1.0f + expf(-t));      // sigmoid(log(x)), matches ref
            s_score[grp][lane] = s;
            s_gid[grp][lane]   = min((int)(s * 10.0f), 9) >> 1;
        }
        __syncwarp();
        if (lane == 0) {
            float gsize[NG] = {0.f, 0.f, 0.f, 0.f, 0.f};
            #pragma unroll
            for (int v = 0; v < NV; ++v)
                gsize[s_gid[grp][v]] += 1.0f;
            float gscore[NG];
            float ssum = 0.f;
            #pragma unroll
            for (int g = 0; g < NG; ++g) {
                float acc = 0.f;
                #pragma unroll
                for (int v = 0; v < NV; ++v)
                    if (s_gid[grp][v] == g) acc += ceilf(s_score[grp][v] * gsize[g]);
                gscore[g] = acc / (gsize[g] + EPSF);
                ssum += gscore[g];
            }
            const float inv = 1.0f / (ssum + EPSF);
            #pragma unroll
            for (int v = 0; v < NV; ++v)
                s_coeff[grp][v] = gscore[s_gid[grp][v]] * inv / (gsize[s_gid[grp][v]] + EPSF);
        }
    }
    __syncthreads();

    // ---- Weighted sum from registers, one STG.128 ----
    float4 acc;
    float c = s_coeff[grp][0];
    acc.x = c * r[0].x; acc.y = c * r[0].y; acc.z = c * r[0].z; acc.w = c * r[0].w;
    #pragma unroll
    for (int v = 1; v < NV; ++v) {
        c = s_coeff[grp][v];
        acc.x = fmaf(c, r[v].x, acc.x);
        acc.y = fmaf(c, r[v].y, acc.y);
        acc.z = fmaf(c, r[v].z, acc.z);
        acc.w = fmaf(c, r[v].w, acc.w);
    }
    reinterpret_cast<float4*>(out)[(size_t)n * (NC / 4) + gt] = acc;
}

extern "C" void kernel_launch(void* const* d_in, const int* in_sizes, int n_in,
                              void* d_out, int out_size)
{
    const float* RPs = (const float*)d_in[0];
    const float* w   = (const float*)d_in[1];
    const float* b   = (const float*)d_in[2];
    float*       out = (float*)d_out;
    (void)in_sizes; (void)n_in; (void)out_size;

    gvcnn_kernel<<<8192 / ROWS_PER_CTA, 256>>>(RPs, w, b, out);
}

// round 4
// speedup vs baseline: 3.0306x; 2.2573x over previous
#include <cuda_runtime.h>
#include <cuda_bf16.h>

// GVCNN group pooling: out[n,c] = sum_v coeff[n,v] * RPs[n,v,c].
// ONE WARP PER ROW, no shared memory, no __syncthreads:
//   - lane l owns channels {4l..4l+3} and {128+4l..128+4l+3} (2x float4)
//   - per-view dot: register pre-reduce + 5-round butterfly (all lanes end
//     with all 12 sums)
//   - bin logic entirely in-warp: ballot/popc for group sizes, packed
//     __reduce_add_sync for group score sums, shfl broadcast for coeffs
//   - weighted sum RELOADS the row (L1/L2 hit, ~500cyc reuse distance) so no
//     registers are held across the score phase -> high occupancy
// Fully independent warps -> memory latency hidden by occupancy, not barriers.

#define NV 12
#define NC 256
#define NG 5
#define EPSF 1e-6f
#define FULL 0xffffffffu

__global__ __launch_bounds__(256)
void gvcnn_kernel(const float* __restrict__ RPs,
                  const float* __restrict__ w,
                  const float* __restrict__ b,
                  float* __restrict__ out)
{
    const int lane = threadIdx.x & 31;
    const int n    = blockIdx.x * 8 + (threadIdx.x >> 5);   // row for this warp

    const float4* row4 = reinterpret_cast<const float4*>(RPs + (size_t)n * (NV * NC));
    const float4* w4   = reinterpret_cast<const float4*>(w);
    const float4  wa   = w4[lane];
    const float4  wb   = w4[lane + 32];

    // ---- Per-view dot partials (data not retained) ----
    float part[NV];
    #pragma unroll
    for (int v = 0; v < NV; ++v) {
        const float4 a  = row4[v * (NC / 4) + lane];
        const float4 b2 = row4[v * (NC / 4) + 32 + lane];
        float p = a.x * wa.x;
        p = fmaf(a.y, wa.y, p);
        p = fmaf(a.z, wa.z, p);
        p = fmaf(a.w, wa.w, p);
        p = fmaf(b2.x, wb.x, p);
        p = fmaf(b2.y, wb.y, p);
        p = fmaf(b2.z, wb.z, p);
        part[v] = fmaf(b2.w, wb.w, p);
    }

    // ---- Butterfly reduce: every lane ends with all 12 row sums ----
    #pragma unroll
    for (int off = 16; off > 0; off >>= 1) {
        #pragma unroll
        for (int v = 0; v < NV; ++v)
            part[v] += __shfl_xor_sync(FULL, part[v], off);
    }

    // ---- Lane v computes score/bin for view v (select chain, no dyn index) ----
    float y = part[0];
    #pragma unroll
    for (int v = 1; v < NV; ++v)
        y = (lane == v) ? part[v] : y;

    const bool  act = lane < NV;
    const float x   = fabsf(y + __ldg(b)) + EPSF;
    const float t   = logf(x);
    const float s   = 1.0f / (1.0f + expf(-t));       // sigmoid(log(x)) as ref
    const int   gid = min((int)(s * 10.0f), 9) >> 1;  // bin 0..4

    // group sizes via ballot/popc (lanes >= NV excluded)
    float gs[NG];
    #pragma unroll
    for (int g = 0; g < NG; ++g)
        gs[g] = (float)__popc(__ballot_sync(FULL, act && (gid == g)));

    // my group's size (select chain)
    float gsz = gs[0];
    #pragma unroll
    for (int g = 1; g < NG; ++g)
        gsz = (gid == g) ? gs[g] : gsz;

    // ceil term, packed group sums via REDUX (term <= 12, sum/group <= 144)
    int term = act ? (int)ceilf(s * gsz) : 0;
    unsigned A = (act && gid < 4) ? ((unsigned)term << (8 * gid)) : 0u;
    unsigned B = (act && gid == 4) ? (unsigned)term : 0u;
    A = __reduce_add_sync(FULL, A);
    B = __reduce_add_sync(FULL, B);

    float gsc[NG];
    gsc[0] = (float)( A        & 0xff) / (gs[0] + EPSF);
    gsc[1] = (float)((A >> 8)  & 0xff) / (gs[1] + EPSF);
    gsc[2] = (float)((A >> 16) & 0xff) / (gs[2] + EPSF);
    gsc[3] = (float)((A >> 24) & 0xff) / (gs[3] + EPSF);
    gsc[4] = (float)B                  / (gs[4] + EPSF);

    const float ssum = gsc[0] + gsc[1] + gsc[2] + gsc[3] + gsc[4];
    const float inv  = 1.0f / (ssum + EPSF);

    // per-group coefficient, then my view's coefficient (select chain)
    float cg[NG];
    #pragma unroll
    for (int g = 0; g < NG; ++g)
        cg[g] = gsc[g] * inv / (gs[g] + EPSF);
    float cme = cg[0];
    #pragma unroll
    for (int g = 1; g < NG; ++g)
        cme = (gid == g) ? cg[g] : cme;

    // broadcast coefficients for all 12 views to every lane
    float coeff[NV];
    #pragma unroll
    for (int v = 0; v < NV; ++v)
        coeff[v] = __shfl_sync(FULL, cme, v);

    // ---- Weighted sum: reload row (L1/L2 resident), 2x STG.128 ----
    float4 accA = make_float4(0.f, 0.f, 0.f, 0.f);
    float4 accB = make_float4(0.f, 0.f, 0.f, 0.f);
    #pragma unroll
    for (int v = 0; v < NV; ++v) {
        const float4 a  = row4[v * (NC / 4) + lane];
        const float4 b2 = row4[v * (NC / 4) + 32 + lane];
        const float  c  = coeff[v];
        accA.x = fmaf(c, a.x, accA.x);
        accA.y = fmaf(c, a.y, accA.y);
        accA.z = fmaf(c, a.z, accA.z);
        accA.w = fmaf(c, a.w, accA.w);
        accB.x = fmaf(c, b2.x, accB.x);
        accB.y = fmaf(c, b2.y, accB.y);
        accB.z = fmaf(c, b2.z, accB.z);
        accB.w = fmaf(c, b2.w, accB.w);
    }
    float4* out4 = reinterpret_cast<float4*>(out);
    out4[(size_t)n * (NC / 4) + lane]      = accA;
    out4[(size_t)n * (NC / 4) + 32 + lane] = accB;
}

extern "C" void kernel_launch(void* const* d_in, const int* in_sizes, int n_in,
                              void* d_out, int out_size)
{
    const float* RPs = (const float*)d_in[0];
    const float* w   = (const float*)d_in[1];
    const float* b   = (const float*)d_in[2];
    float*       out = (float*)d_out;
    (void)in_sizes; (void)n_in; (void)out_size;

    gvcnn_kernel<<<8192 / 8, 256>>>(RPs, w, b, out);
}